// round 9
// baseline (speedup 1.0000x reference)
#include <cuda_runtime.h>

#define T_DIM 4096
#define D_DIM 64
#define B_DIM 32
#define BLK 128

// pm tile in shared memory: row w (0..62), 128 consecutive t per block.
// Access spm[w*BLK + tid] -> lane-consecutive, conflict-free.

// One pyramid level (windows W = M .. 2M-1).
//  - w[] : gated duration weights, batch-loaded (register array, high MLP)
//  - peeled j=M-1: C build only (its fine term has suf=0; peeling also keeps
//    pm reads within rows 0..62 of the smem tile)
//  - j-loop: builds C[j], adds fine terms (a*pm[2j] + b*pm[2j+1]) * suf_{j+1}
//  - k-loop: coarse correlation  res += pm[k] * sum_p w[p]*C[k-p]
template<int M, int FS>
__device__ __forceinline__ void level_sm(const float* __restrict__ F,
                                         float* __restrict__ C,
                                         const float* __restrict__ pmt,   // smem + tid
                                         const float* __restrict__ dmb,
                                         int low, int up,
                                         float& r0, float& r1)
{
    float w[M];
#pragma unroll
    for (int p = 0; p < M; p++) {
        const int W = M + p;
        w[p] = (W >= low && W < up) ? dmb[(W - 1) * T_DIM] : 0.f;
    }

    // peeled top element: no fine term (suf would be 0), no pm read
    C[M - 1] = 0.5f * (F[(2 * M - 2) * FS] + F[(2 * M - 1) * FS]);

    // fine terms + C build (descending j); suf = sum_{q >= j+1} w[q]
    float suf = 0.f;
#pragma unroll
    for (int j = M - 2; j >= 0; j--) {
        suf += w[j + 1];
        const float a = F[(2 * j) * FS];
        const float b = F[(2 * j + 1) * FS];
        C[j] = 0.5f * (a + b);
        r1 = fmaf(fmaf(a, pmt[(2 * j) * BLK], b * pmt[(2 * j + 1) * BLK]), suf, r1);
    }

    // coarse correlation, k descending (pm rows 0..2M-2 <= 62); dual accumulators
#pragma unroll
    for (int k = 2 * M - 2; k >= 0; k--) {
        const int pmin = (k - (M - 1) > 0) ? k - (M - 1) : 0;
        const int pmax = k / 2;
        float coef = 0.f;
#pragma unroll
        for (int p = pmin; p <= pmax; p++)
            coef = fmaf(w[p], C[k - p], coef);
        if (k & 1) r1 = fmaf(pmt[k * BLK], coef, r1);
        else       r0 = fmaf(pmt[k * BLK], coef, r0);
    }
}

__global__ __launch_bounds__(BLK, 6)
void ContextGenerator_34875134444049_kernel(const float* __restrict__ rep,
                                            const float* __restrict__ dmask,
                                            const float* __restrict__ pmask,
                                            const int* __restrict__ lowp,
                                            const int* __restrict__ upp,
                                            float* __restrict__ out)
{
    __shared__ float spm[63 * BLK];   // 31.5 KB, rows 0..62

    const int tid  = threadIdx.x;
    const int gid  = blockIdx.x * BLK + tid;     // 0 .. B*T-1
    const int b    = gid >> 12;                  // T = 4096
    const int t    = gid & (T_DIM - 1);
    const int base = b * (D_DIM * T_DIM) + t;

    const float* __restrict__ pmb = pmask + base;
    const float* __restrict__ dmb = dmask + base;

    // Scalar cooperative staging: per-warp each row access coalesces to the
    // same 128B lines as a vector load; no alignment preconditions.
#pragma unroll
    for (int w = 0; w < 63; w++) spm[w * BLK + tid] = pmb[w * T_DIM];
    __syncthreads();

    const int low = *lowp;
    const int up  = *upp;

    const float* __restrict__ pmt = spm + tid;

    float r0 = 0.f, r1 = 0.f;

    float C1[32]; level_sm<32, T_DIM>(rep + base, C1, pmt, dmb, low, up, r0, r1);
    float C2[16]; level_sm<16, 1>(C1, C2, pmt, dmb, low, up, r0, r1);
    float C3[8];  level_sm<8, 1>(C2, C3, pmt, dmb, low, up, r0, r1);
    float C4[4];  level_sm<4, 1>(C3, C4, pmt, dmb, low, up, r0, r1);
    float C5[2];  level_sm<2, 1>(C4, C5, pmt, dmb, low, up, r0, r1);

    // W = 1: d = deepest coarse level (single element)
    const float x6 = 0.5f * (C5[0] + C5[1]);
    if (1 >= low && 1 < up) r0 = fmaf(dmb[0], x6 * pmt[0], r0);

    out[gid] = r0 + r1;   // [B, 1, T] flat = gid
}

extern "C" void kernel_launch(void* const* d_in, const int* in_sizes, int n_in,
                              void* d_out, int out_size)
{
    const float* rep   = (const float*)d_in[0];
    const float* dmask = (const float*)d_in[1];
    const float* pmask = (const float*)d_in[2];
    const int*   lowp  = (const int*)d_in[3];
    const int*   upp   = (const int*)d_in[4];
    float* out = (float*)d_out;

    const int total = B_DIM * T_DIM;           // 131072
    ContextGenerator_34875134444049_kernel<<<total / BLK, BLK>>>(
        rep, dmask, pmask, lowp, upp, out);
}

// round 10
// speedup vs baseline: 2.4451x; 2.4451x over previous
#include <cuda_runtime.h>

#define T_DIM 4096
#define D_DIM 64
#define B_DIM 32

// One pyramid level: fine F[2M] (compile-time stride FS) -> coarse C[M],
// windows W = M .. 2M-1.
//
// Key change vs R1/R2: the gated duration weights w[p] are BATCH-loaded into
// a register array before the compute loop (32/16/8/4/2 back-to-back LDGs,
// high MLP) instead of one dependent load per p-iteration (the serial-latency
// killer identified in R9's post-mortem). In the descending-p loop w[p] dies
// exactly as C[p-1] is born, so live(w)+live(C) stays ~M+1 and peak pressure
// matches R1's proven-tolerable regime.
template<int M, int FS>
__device__ __forceinline__ void transition(const float* __restrict__ F,
                                           float* __restrict__ C,
                                           const float* __restrict__ pmv,
                                           const float* __restrict__ dmb,
                                           int low, int up,
                                           float& r0, float& r1)
{
    // batched gated dm loads (unconditional LDG + select -> batchable)
    float w[M];
#pragma unroll
    for (int p = 0; p < M; p++) {
        const int W = M + p;
        const float v = dmb[(W - 1) * T_DIM];
        w[p] = (W >= low && W < up) ? v : 0.f;
    }

    C[M - 1] = 0.5f * (F[(2 * M - 2) * FS] + F[(2 * M - 1) * FS]);
    float suf = 0.f;
#pragma unroll
    for (int p = M - 1; p >= 1; p--) {
        float sc = 0.f;
#pragma unroll
        for (int j = p; j < M; j++) sc = fmaf(C[j], pmv[j + p], sc);
        r0 = fmaf(w[p], sc, r0);
        suf += w[p];
        const float a = F[(2 * p - 2) * FS], b = F[(2 * p - 1) * FS];
        r1 = fmaf(fmaf(a, pmv[2 * p - 2], b * pmv[2 * p - 1]), suf, r1);
        C[p - 1] = 0.5f * (a + b);
    }
    float sc = 0.f;
#pragma unroll
    for (int j = 0; j < M; j++) sc = fmaf(C[j], pmv[j], sc);
    r0 = fmaf(w[0], sc, r0);
}

__global__ __launch_bounds__(256)
void ContextGenerator_34875134444049_kernel(const float* __restrict__ rep,
                                            const float* __restrict__ dmask,
                                            const float* __restrict__ pmask,
                                            const int* __restrict__ lowp,
                                            const int* __restrict__ upp,
                                            float* __restrict__ out)
{
    const int gid = blockIdx.x * 256 + threadIdx.x;   // 0 .. B*T-1
    const int b = gid >> 12;                          // T = 4096
    const int t = gid & (T_DIM - 1);
    const int base = b * (D_DIM * T_DIM) + t;

    const int low = *lowp;
    const int up  = *upp;

    const float* __restrict__ pmb = pmask + base;
    const float* __restrict__ dmb = dmask + base;

    // pm[63] is dead (fine terms reach pm[61], coarse reach pm[62])
    float pmv[63];
#pragma unroll
    for (int w = 0; w < 63; w++) pmv[w] = pmb[w * T_DIM];

    float r0 = 0.f, r1 = 0.f;

    float L1[32]; transition<32, T_DIM>(rep + base, L1, pmv, dmb, low, up, r0, r1);
    float L2[16]; transition<16, 1>(L1, L2, pmv, dmb, low, up, r0, r1);
    float L3[8];  transition<8, 1>(L2, L3, pmv, dmb, low, up, r0, r1);
    float L4[4];  transition<4, 1>(L3, L4, pmv, dmb, low, up, r0, r1);
    float L5[2];  transition<2, 1>(L4, L5, pmv, dmb, low, up, r0, r1);

    // W = 1: d = deepest level (single element)
    const float x6 = 0.5f * (L5[0] + L5[1]);
    if (1 >= low && 1 < up) r0 = fmaf(dmb[0], x6 * pmv[0], r0);

    out[gid] = r0 + r1;   // [B, 1, T] flat = gid
}

extern "C" void kernel_launch(void* const* d_in, const int* in_sizes, int n_in,
                              void* d_out, int out_size)
{
    const float* rep   = (const float*)d_in[0];
    const float* dmask = (const float*)d_in[1];
    const float* pmask = (const float*)d_in[2];
    const int*   lowp  = (const int*)d_in[3];
    const int*   upp   = (const int*)d_in[4];
    float* out = (float*)d_out;

    const int total = B_DIM * T_DIM;           // 131072
    ContextGenerator_34875134444049_kernel<<<total / 256, 256>>>(
        rep, dmask, pmask, lowp, upp, out);
}